// round 1
// baseline (speedup 1.0000x reference)
#include <cuda_runtime.h>
#include <math.h>

#define B_ROWS 32768
#define D_IN   256
#define D_H    512
#define D_Q    1024
#define D_E    256

// ---- scratch (device globals: no allocation allowed) ----
__device__ float g_h1[(size_t)B_ROWS * D_H];      // h1 / hk1 / hd (reused)
__device__ float g_h2[(size_t)B_ROWS * D_H];      // hk2
__device__ float g_logits[(size_t)B_ROWS * D_Q];  // logits (khot fallback in-place)
__device__ float g_q[(size_t)B_ROWS * D_E];       // q
__device__ float g_kclip[B_ROWS];
__device__ float g_invk[B_ROWS];

// =====================================================================
// fp32 SGEMM: C[M,N] = act( A @ W^T + bias ) * rowScale
//   A row-major (optionally two K-segments A0[:,0:K0], A1[:,K0:K])
//   W row-major [N,K]
// =====================================================================
#define BM 128
#define BN 128
#define BK 16
#define TM 8
#define TN 8

__global__ void __launch_bounds__(256, 2)
sgemm_kernel(int N, int K,
             const float* __restrict__ A0, int lda0, int K0,
             const float* __restrict__ A1, int lda1,
             const float* __restrict__ W,
             const float* __restrict__ bias,
             const float* __restrict__ rowScale,
             float* __restrict__ C, int ldc, int do_relu)
{
    __shared__ float As[2][BK][BM];
    __shared__ float Bs[2][BK][BN];

    const int tid  = threadIdx.x;
    const int bm   = blockIdx.y * BM;
    const int bn   = blockIdx.x * BN;
    const int tm   = (tid >> 4) * TM;
    const int tn   = (tid & 15) * TN;
    const int lrow = tid >> 2;          // 0..63
    const int lcol = (tid & 3) << 2;    // 0,4,8,12

    float acc[TM][TN];
#pragma unroll
    for (int i = 0; i < TM; ++i)
#pragma unroll
        for (int j = 0; j < TN; ++j) acc[i][j] = 0.f;

    const int nT = K / BK;
    float4 a0, a1, b0, b1;

#define FETCH(t) do {                                                         \
    int k0_ = (t) * BK;                                                       \
    const float* Ap_; int la_; int kk_;                                       \
    if (k0_ < K0) { Ap_ = A0; la_ = lda0; kk_ = k0_; }                        \
    else          { Ap_ = A1; la_ = lda1; kk_ = k0_ - K0; }                   \
    a0 = *(const float4*)(Ap_ + (size_t)(bm + lrow)      * la_ + kk_ + lcol); \
    a1 = *(const float4*)(Ap_ + (size_t)(bm + lrow + 64) * la_ + kk_ + lcol); \
    b0 = *(const float4*)(W   + (size_t)(bn + lrow)      * K   + k0_ + lcol); \
    b1 = *(const float4*)(W   + (size_t)(bn + lrow + 64) * K   + k0_ + lcol); \
} while (0)

#define STASH(bf) do {                                        \
    As[bf][lcol+0][lrow]    = a0.x; As[bf][lcol+1][lrow]    = a0.y; \
    As[bf][lcol+2][lrow]    = a0.z; As[bf][lcol+3][lrow]    = a0.w; \
    As[bf][lcol+0][lrow+64] = a1.x; As[bf][lcol+1][lrow+64] = a1.y; \
    As[bf][lcol+2][lrow+64] = a1.z; As[bf][lcol+3][lrow+64] = a1.w; \
    Bs[bf][lcol+0][lrow]    = b0.x; Bs[bf][lcol+1][lrow]    = b0.y; \
    Bs[bf][lcol+2][lrow]    = b0.z; Bs[bf][lcol+3][lrow]    = b0.w; \
    Bs[bf][lcol+0][lrow+64] = b1.x; Bs[bf][lcol+1][lrow+64] = b1.y; \
    Bs[bf][lcol+2][lrow+64] = b1.z; Bs[bf][lcol+3][lrow+64] = b1.w; \
} while (0)

    FETCH(0);
    STASH(0);
    __syncthreads();

    int buf = 0;
    for (int t = 0; t < nT; ++t) {
        if (t + 1 < nT) FETCH(t + 1);
#pragma unroll
        for (int kk = 0; kk < BK; ++kk) {
            float a[TM], b[TN];
            *(float4*)&a[0] = *(const float4*)&As[buf][kk][tm];
            *(float4*)&a[4] = *(const float4*)&As[buf][kk][tm + 4];
            *(float4*)&b[0] = *(const float4*)&Bs[buf][kk][tn];
            *(float4*)&b[4] = *(const float4*)&Bs[buf][kk][tn + 4];
#pragma unroll
            for (int i = 0; i < TM; ++i)
#pragma unroll
                for (int j = 0; j < TN; ++j)
                    acc[i][j] += a[i] * b[j];
        }
        if (t + 1 < nT) STASH(buf ^ 1);
        __syncthreads();
        buf ^= 1;
    }

    float bj[TN];
#pragma unroll
    for (int j = 0; j < TN; ++j) bj[j] = bias ? bias[bn + tn + j] : 0.f;

#pragma unroll
    for (int i = 0; i < TM; ++i) {
        const int row = bm + tm + i;
        const float rs = rowScale ? rowScale[row] : 1.f;
        float v[TN];
#pragma unroll
        for (int j = 0; j < TN; ++j) {
            float t = acc[i][j] + bj[j];
            if (do_relu) t = fmaxf(t, 0.f);
            v[j] = t * rs;
        }
        float* cp = C + (size_t)row * ldc + bn + tn;
        *(float4*)cp       = make_float4(v[0], v[1], v[2], v[3]);
        *(float4*)(cp + 4) = make_float4(v[4], v[5], v[6], v[7]);
    }
#undef FETCH
#undef STASH
}

// =====================================================================
// k-predictor final layer: k = clip(sigmoid(h.w+b)*1024*sigmoid(ks)*2, 1, 1024)
// one warp per row
// =====================================================================
__global__ void kpred_kernel(const float* __restrict__ hk2,
                             const float* __restrict__ wk3,
                             const float* __restrict__ bk3,
                             const float* __restrict__ kscale,
                             float* __restrict__ kclip,
                             float* __restrict__ invk,
                             float* __restrict__ kout)
{
    __shared__ float ws[D_H];
    for (int j = threadIdx.x; j < D_H; j += blockDim.x) ws[j] = wk3[j];
    __syncthreads();

    const int warp = blockIdx.x * (blockDim.x >> 5) + (threadIdx.x >> 5);
    const int lane = threadIdx.x & 31;
    if (warp >= B_ROWS) return;

    const float* h = hk2 + (size_t)warp * D_H;
    float s = 0.f;
    for (int j = lane; j < D_H; j += 32) s += h[j] * ws[j];
#pragma unroll
    for (int o = 16; o; o >>= 1) s += __shfl_xor_sync(0xffffffffu, s, o);

    if (lane == 0) {
        float z  = s + bk3[0];
        float k  = (1.f / (1.f + expf(-z))) * 1024.f;
        float ks = 1.f / (1.f + expf(-kscale[0]));
        k = k * ks * 2.f;
        k = fminf(fmaxf(k, 1.f), 1024.f);
        kclip[warp] = k;
        invk[warp]  = 1.f / k;
        if (kout) kout[warp] = k;
    }
}

// =====================================================================
// Exact dynamic-top-k one-hot (stable descending argsort semantics).
// One block of 256 threads per row; MSB-first 8-bit radix select.
// =====================================================================
__global__ void topk_kernel(const float* __restrict__ logits,
                            const float* __restrict__ kclip,
                            float* __restrict__ khot)
{
    __shared__ unsigned keys[D_Q];
    __shared__ int hist[256];
    __shared__ int scanbuf[256];
    __shared__ int warpsum[8];
    __shared__ int sBin;

    const int row = blockIdx.x;
    const int tid = threadIdx.x;
    const float* lr = logits + (size_t)row * D_Q;

    // load 4 contiguous logits, convert to order-preserving uint keys
    float4 v = ((const float4*)lr)[tid];
    {
        unsigned u;
        u = __float_as_uint(v.x); keys[tid*4+0] = (int)u >= 0 ? (u | 0x80000000u) : ~u;
        u = __float_as_uint(v.y); keys[tid*4+1] = (int)u >= 0 ? (u | 0x80000000u) : ~u;
        u = __float_as_uint(v.z); keys[tid*4+2] = (int)u >= 0 ? (u | 0x80000000u) : ~u;
        u = __float_as_uint(v.w); keys[tid*4+3] = (int)u >= 0 ? (u | 0x80000000u) : ~u;
    }

    float kc = kclip[row];
    int c = (int)ceilf(kc);
    c = max(1, min(D_Q, c));
    __syncthreads();

    unsigned prefix = 0;
    int want = c;
#pragma unroll
    for (int byte = 3; byte >= 0; --byte) {
        hist[tid] = 0;
        __syncthreads();
        const unsigned mask = (byte == 3) ? 0u : (0xFFFFFFFFu << ((byte + 1) * 8));
#pragma unroll
        for (int e = 0; e < 4; ++e) {
            unsigned kk = keys[tid * 4 + e];
            if ((kk & mask) == prefix)
                atomicAdd(&hist[(kk >> (byte * 8)) & 0xFF], 1);
        }
        __syncthreads();
        // inclusive suffix sum over 256 bins
        scanbuf[tid] = hist[tid];
        __syncthreads();
        for (int d = 1; d < 256; d <<= 1) {
            int add = (tid + d < 256) ? scanbuf[tid + d] : 0;
            __syncthreads();
            scanbuf[tid] += add;
            __syncthreads();
        }
        int nb = (tid < 255) ? scanbuf[tid + 1] : 0;
        if (scanbuf[tid] >= want && nb < want) sBin = tid;
        __syncthreads();
        int bin = sBin;
        int greater = (bin < 255) ? scanbuf[bin + 1] : 0;
        want -= greater;
        prefix |= ((unsigned)bin) << (byte * 8);
        __syncthreads();
    }

    const unsigned thr = prefix;   // exact c-th largest key
    const int rem = want;          // how many ==thr to take (ascending index)

    int gtf[4], eqf[4], pre[4];
    int lc = 0;
#pragma unroll
    for (int e = 0; e < 4; ++e) {
        unsigned kk = keys[tid * 4 + e];
        gtf[e] = (kk > thr);
        eqf[e] = (kk == thr);
        pre[e] = lc;
        lc += eqf[e];
    }
    // exclusive block scan of equals-count (index order preserved)
    const int lane = tid & 31, wid = tid >> 5;
    int inc = lc;
#pragma unroll
    for (int o = 1; o < 32; o <<= 1) {
        int y = __shfl_up_sync(0xffffffffu, inc, o);
        if (lane >= o) inc += y;
    }
    if (lane == 31) warpsum[wid] = inc;
    __syncthreads();
    if (tid == 0) {
        int run = 0;
        for (int i = 0; i < 8; ++i) { int t = warpsum[i]; warpsum[i] = run; run += t; }
    }
    __syncthreads();
    const int base = warpsum[wid] + inc - lc;

    float4 o;
    o.x = (gtf[0] || (eqf[0] && (base + pre[0]) < rem)) ? 1.f : 0.f;
    o.y = (gtf[1] || (eqf[1] && (base + pre[1]) < rem)) ? 1.f : 0.f;
    o.z = (gtf[2] || (eqf[2] && (base + pre[2]) < rem)) ? 1.f : 0.f;
    o.w = (gtf[3] || (eqf[3] && (base + pre[3]) < rem)) ? 1.f : 0.f;
    ((float4*)(khot + (size_t)row * D_Q))[tid] = o;
}

__global__ void tail_kernel(float* zptr) { *zptr = 0.f; }

// =====================================================================
extern "C" void kernel_launch(void* const* d_in, const int* in_sizes, int n_in,
                              void* d_out, int out_size)
{
    const float* x      = (const float*)d_in[0];
    const float* We1    = (const float*)d_in[1];
    const float* be1    = (const float*)d_in[2];
    const float* We2    = (const float*)d_in[3];
    const float* be2    = (const float*)d_in[4];
    const float* Wcb    = (const float*)d_in[5];
    const float* Wd1    = (const float*)d_in[6];
    const float* bd1    = (const float*)d_in[7];
    const float* Wd2    = (const float*)d_in[8];
    const float* bd2    = (const float*)d_in[9];
    const float* Wk1    = (const float*)d_in[10];
    const float* bk1    = (const float*)d_in[11];
    const float* Wk2    = (const float*)d_in[12];
    const float* bk2    = (const float*)d_in[13];
    const float* Wk3    = (const float*)d_in[14];
    const float* bk3    = (const float*)d_in[15];
    const float* kscale = (const float*)d_in[16];

    float *h1, *h2, *logits, *q, *kclip, *invk;
    cudaGetSymbolAddress((void**)&h1, g_h1);
    cudaGetSymbolAddress((void**)&h2, g_h2);
    cudaGetSymbolAddress((void**)&logits, g_logits);
    cudaGetSymbolAddress((void**)&q, g_q);
    cudaGetSymbolAddress((void**)&kclip, g_kclip);
    cudaGetSymbolAddress((void**)&invk, g_invk);

    float* out = (float*)d_out;
    const long long reconN = (long long)B_ROWS * D_IN;
    const long long khotN  = (long long)B_ROWS * D_Q;
    const long long osz    = (long long)out_size;

    float* khot = logits;                    // fallback: in-place over logits
    if (osz >= reconN + khotN) khot = out + reconN;
    float* kout = nullptr;
    float* zptr = nullptr;
    const long long tail = osz - (reconN + khotN);
    if (tail == 1 + (long long)B_ROWS)      { zptr = out + reconN + khotN; kout = zptr + 1; }
    else if (tail == (long long)B_ROWS)     { kout = out + reconN + khotN; }

    const dim3 blk(256);
    const int GY = B_ROWS / BM;

    // h1 = relu(x @ We1^T + be1)
    sgemm_kernel<<<dim3(D_H / BN, GY), blk>>>(D_H, D_IN, x, D_IN, D_IN,
                                              nullptr, 0, We1, be1, nullptr, h1, D_H, 1);
    // logits = h1 @ We2^T + be2
    sgemm_kernel<<<dim3(D_Q / BN, GY), blk>>>(D_Q, D_H, h1, D_H, D_H,
                                              nullptr, 0, We2, be2, nullptr, logits, D_Q, 0);
    // hk1 = relu([x, logits] @ Wk1^T + bk1)   (segmented K: 256 + 1024)
    sgemm_kernel<<<dim3(D_H / BN, GY), blk>>>(D_H, D_IN + D_Q, x, D_IN, D_IN,
                                              logits, D_Q, Wk1, bk1, nullptr, h1, D_H, 1);
    // hk2 = relu(hk1 @ Wk2^T + bk2)
    sgemm_kernel<<<dim3(D_H / BN, GY), blk>>>(D_H, D_H, h1, D_H, D_H,
                                              nullptr, 0, Wk2, bk2, nullptr, h2, D_H, 1);
    // k, 1/k
    kpred_kernel<<<B_ROWS / 8, 256>>>(h2, Wk3, bk3, kscale, kclip, invk, kout);
    // khot
    topk_kernel<<<B_ROWS, 256>>>(logits, kclip, khot);
    // q = (khot @ Wcb^T) * (1/k)
    sgemm_kernel<<<dim3(D_E / BN, GY), blk>>>(D_E, D_Q, khot, D_Q, D_Q,
                                              nullptr, 0, Wcb, nullptr, invk, q, D_E, 0);
    // hd = relu(q @ Wd1^T + bd1)
    sgemm_kernel<<<dim3(D_H / BN, GY), blk>>>(D_H, D_E, q, D_E, D_E,
                                              nullptr, 0, Wd1, bd1, nullptr, h1, D_H, 1);
    // recon = hd @ Wd2^T + bd2  -> d_out
    sgemm_kernel<<<dim3(D_IN / BN, GY), blk>>>(D_IN, D_H, h1, D_H, D_H,
                                               nullptr, 0, Wd2, bd2, nullptr, out, D_IN, 0);
    if (zptr) tail_kernel<<<1, 1>>>(zptr);
}